// round 1
// baseline (speedup 1.0000x reference)
#include <cuda_runtime.h>
#include <math.h>

// Problem constants
#define BB   4
#define NN   512
#define DD   1024
#define HH   16
#define HD   64
#define HID  4096
#define TOK  (BB*NN)      // 2048
#define MODD (6*DD)       // 6144

// ---------------- scratch (static device globals; no allocation) ------------
__device__ float g_mod[BB*MODD];              // [4, 6144]
__device__ float g_xn[TOK*DD];                // normalized/modulated activations
__device__ float g_qkv[TOK*3*DD];             // [2048, 3072]
__device__ float g_bias[(size_t)BB*HH*NN*NN]; // [B,H,N,N]  64 MB
__device__ float g_S[(size_t)BB*HH*NN*NN];    // scores / probs (in-place softmax)
__device__ float g_attnout[TOK*DD];           // attention output (token-major)
__device__ float g_x1[TOK*DD];                // x after attention residual
__device__ float g_h[TOK*HID];                // MLP hidden

// ---------------- adaLN modulation: mod = silu(t_emb) @ w_ada^T + b_ada -----
// one warp per output element (b, o)
__global__ void k_mod(const float* __restrict__ t_emb,
                      const float* __restrict__ w_ada,
                      const float* __restrict__ b_ada) {
    int warp = (blockIdx.x * blockDim.x + threadIdx.x) >> 5;
    int lane = threadIdx.x & 31;
    if (warp >= BB * MODD) return;
    int b = warp / MODD;
    int o = warp % MODD;
    const float* te = t_emb + b * DD;
    const float* w  = w_ada + (size_t)o * DD;
    float acc = 0.f;
    for (int k = lane; k < DD; k += 32) {
        float t = te[k];
        float s = t / (1.f + expf(-t));   // silu
        acc += s * w[k];
    }
    #pragma unroll
    for (int off = 16; off; off >>= 1)
        acc += __shfl_xor_sync(0xffffffffu, acc, off);
    if (lane == 0) g_mod[b * MODD + o] = acc + b_ada[o];
}

// ---------------- LayerNorm + adaLN modulate --------------------------------
// out = LN(x)*g+beta, then *(1+scale)+shift ; one block per token (256 thr)
__global__ void k_ln_mod(const float* __restrict__ x,
                         const float* __restrict__ g,
                         const float* __restrict__ beta,
                         int shift_off, int scale_off,
                         float* __restrict__ out) {
    int t = blockIdx.x;
    int b = t >> 9;           // N = 512
    const float* xr = x + (size_t)t * DD;
    float v[4];
    float s = 0.f, ss = 0.f;
    #pragma unroll
    for (int i = 0; i < 4; i++) {
        v[i] = xr[threadIdx.x + i * 256];
        s  += v[i];
        ss += v[i] * v[i];
    }
    __shared__ float shs[8], shss[8];
    #pragma unroll
    for (int o = 16; o; o >>= 1) {
        s  += __shfl_xor_sync(0xffffffffu, s,  o);
        ss += __shfl_xor_sync(0xffffffffu, ss, o);
    }
    int w = threadIdx.x >> 5, l = threadIdx.x & 31;
    if (l == 0) { shs[w] = s; shss[w] = ss; }
    __syncthreads();
    if (w == 0) {
        s  = (l < 8) ? shs[l]  : 0.f;
        ss = (l < 8) ? shss[l] : 0.f;
        #pragma unroll
        for (int o = 4; o; o >>= 1) {
            s  += __shfl_xor_sync(0xffffffffu, s,  o);
            ss += __shfl_xor_sync(0xffffffffu, ss, o);
        }
        if (l == 0) { shs[0] = s; shss[0] = ss; }
    }
    __syncthreads();
    float mu  = shs[0] * (1.f / DD);
    float var = shss[0] * (1.f / DD) - mu * mu;
    float r   = rsqrtf(var + 1e-5f);
    const float* shiftp = g_mod + b * MODD + shift_off;
    const float* scalep = g_mod + b * MODD + scale_off;
    #pragma unroll
    for (int i = 0; i < 4; i++) {
        int d = threadIdx.x + i * 256;
        float xn = (v[i] - mu) * r * g[d] + beta[d];
        out[(size_t)t * DD + d] = xn * (1.f + scalep[d]) + shiftp[d];
    }
}

// ---------------- generic tiled GEMM: C = A[M,K] @ W[N,K]^T + bias ----------
// MODE 0: C = acc + bias
// MODE 1: C = resid + gate * (acc + bias)   (gate from g_mod chunk, N must be 1024)
// MODE 2: C = gelu_exact(acc + bias)
// BM=BN=64, BK=16, 256 threads, 4x4 register blocking.
__global__ void k_gemm_bt(const float* __restrict__ A,
                          const float* __restrict__ W,
                          const float* __restrict__ bias,
                          float* __restrict__ C,
                          int N, int K, int MODE,
                          const float* __restrict__ resid,
                          int gate_off) {
    __shared__ float As[16][68];
    __shared__ float Bs[16][68];
    int row0 = blockIdx.y * 64, col0 = blockIdx.x * 64;
    int tid = threadIdx.x;
    int tx = tid & 15, ty = tid >> 4;
    float acc[4][4] = {};
    for (int k0 = 0; k0 < K; k0 += 16) {
        #pragma unroll
        for (int i = 0; i < 4; i++) {
            int e = tid + i * 256;
            int m = e >> 4, kk = e & 15;
            As[kk][m] = A[(size_t)(row0 + m) * K + k0 + kk];
            Bs[kk][m] = W[(size_t)(col0 + m) * K + k0 + kk];
        }
        __syncthreads();
        #pragma unroll
        for (int k = 0; k < 16; k++) {
            float4 a4 = *(const float4*)&As[k][ty * 4];
            float4 b4 = *(const float4*)&Bs[k][tx * 4];
            float ra[4] = {a4.x, a4.y, a4.z, a4.w};
            float rb[4] = {b4.x, b4.y, b4.z, b4.w};
            #pragma unroll
            for (int i = 0; i < 4; i++)
                #pragma unroll
                for (int j = 0; j < 4; j++)
                    acc[i][j] += ra[i] * rb[j];
        }
        __syncthreads();
    }
    #pragma unroll
    for (int i = 0; i < 4; i++) {
        int r = row0 + ty * 4 + i;
        int c0 = col0 + tx * 4;
        float4 outv;
        float* ov = &outv.x;
        #pragma unroll
        for (int j = 0; j < 4; j++) {
            int c = c0 + j;
            float v = acc[i][j] + bias[c];
            if (MODE == 2) {
                v = 0.5f * v * (1.f + erff(v * 0.70710678118654752f));
            } else if (MODE == 1) {
                int b = r >> 9;
                float gate = g_mod[b * MODD + gate_off + c];
                v = resid[(size_t)r * DD + c] + gate * v;
            }
            ov[j] = v;
        }
        *(float4*)&C[(size_t)r * N + c0] = outv;
    }
}

// ---------------- rel-pos bias MLP: [B,N,N,2] -> [B,H,N,N] -------------------
__global__ void k_bias(const float* __restrict__ rp,
                       const float* __restrict__ w1, const float* __restrict__ b1,
                       const float* __restrict__ w2, const float* __restrict__ b2) {
    __shared__ float sw1[128], sb1[64], sw2[1024], sb2[16];
    int tid = threadIdx.x;
    if (tid < 128) sw1[tid] = w1[tid];
    if (tid < 64)  sb1[tid] = b1[tid];
    for (int i = tid; i < 1024; i += 256) sw2[i] = w2[i];
    if (tid < 16)  sb2[tid] = b2[tid];
    __syncthreads();
    int bi = blockIdx.x;            // b*512 + i
    int b = bi >> 9, i = bi & 511;
    for (int jj = 0; jj < 2; jj++) {
        int j = tid + jj * 256;
        const float* r = rp + ((size_t)bi * NN + j) * 2;
        float r0 = r[0], r1 = r[1];
        float hbuf[64];
        #pragma unroll
        for (int u = 0; u < 64; u++)
            hbuf[u] = fmaxf(0.f, sw1[2*u] * r0 + sw1[2*u+1] * r1 + sb1[u]);
        for (int h = 0; h < 16; h++) {
            float a = sb2[h];
            #pragma unroll
            for (int u = 0; u < 64; u++)
                a += sw2[h * 64 + u] * hbuf[u];
            g_bias[(((size_t)(b * HH + h) * NN) + i) * NN + j] = a;
        }
    }
}

// ---------------- attention scores: S = scale*Q K^T + bias, mask ------------
// grid (8 j-tiles, 8 i-tiles, 64 bh), 64x64 tile, K=64
__global__ void k_scores(const int* __restrict__ amask) {
    int bh = blockIdx.z, b = bh >> 4, h = bh & 15;
    const float* Q  = g_qkv + (size_t)(b * NN) * (3 * DD) + h * HD;
    const float* Kp = Q + DD;
    __shared__ float As[16][68];
    __shared__ float Bs[16][68];
    int i0 = blockIdx.y * 64, j0 = blockIdx.x * 64;
    int tid = threadIdx.x, tx = tid & 15, ty = tid >> 4;
    float acc[4][4] = {};
    for (int k0 = 0; k0 < HD; k0 += 16) {
        #pragma unroll
        for (int i = 0; i < 4; i++) {
            int e = tid + i * 256;
            int m = e >> 4, kk = e & 15;
            As[kk][m] = Q [(size_t)(i0 + m) * (3 * DD) + k0 + kk];
            Bs[kk][m] = Kp[(size_t)(j0 + m) * (3 * DD) + k0 + kk];
        }
        __syncthreads();
        #pragma unroll
        for (int k = 0; k < 16; k++) {
            float4 a4 = *(const float4*)&As[k][ty * 4];
            float4 b4 = *(const float4*)&Bs[k][tx * 4];
            float ra[4] = {a4.x, a4.y, a4.z, a4.w};
            float rb[4] = {b4.x, b4.y, b4.z, b4.w};
            #pragma unroll
            for (int i = 0; i < 4; i++)
                #pragma unroll
                for (int j = 0; j < 4; j++)
                    acc[i][j] += ra[i] * rb[j];
        }
        __syncthreads();
    }
    const float* brow = g_bias + (size_t)bh * NN * NN;
    float*       srow = g_S    + (size_t)bh * NN * NN;
    #pragma unroll
    for (int i = 0; i < 4; i++) {
        int ii = i0 + ty * 4 + i;
        #pragma unroll
        for (int j = 0; j < 4; j++) {
            int jj = j0 + tx * 4 + j;
            float v = acc[i][j] * 0.125f + brow[(size_t)ii * NN + jj];
            if (amask[b * NN + jj] == 0) v = -1e30f;
            srow[(size_t)ii * NN + jj] = v;
        }
    }
}

// ---------------- row softmax over 512, in place -----------------------------
__global__ void k_softmax() {
    size_t row = blockIdx.x;
    float* p = g_S + row * NN;
    int tx = threadIdx.x;  // 128 threads
    float v[4];
    float m = -1e30f;
    #pragma unroll
    for (int i = 0; i < 4; i++) { v[i] = p[tx + i * 128]; m = fmaxf(m, v[i]); }
    __shared__ float sh[4];
    #pragma unroll
    for (int o = 16; o; o >>= 1) m = fmaxf(m, __shfl_xor_sync(0xffffffffu, m, o));
    int w = tx >> 5, l = tx & 31;
    if (l == 0) sh[w] = m;
    __syncthreads();
    m = fmaxf(fmaxf(sh[0], sh[1]), fmaxf(sh[2], sh[3]));
    float s = 0.f;
    #pragma unroll
    for (int i = 0; i < 4; i++) { v[i] = __expf(v[i] - m); s += v[i]; }
    #pragma unroll
    for (int o = 16; o; o >>= 1) s += __shfl_xor_sync(0xffffffffu, s, o);
    if (l == 0) sh[w] = s;
    __syncthreads();
    s = sh[0] + sh[1] + sh[2] + sh[3];
    float inv = 1.f / s;
    #pragma unroll
    for (int i = 0; i < 4; i++) p[tx + i * 128] = v[i] * inv;
}

// ---------------- PV: out[b,i,h,:] = P[bh] @ V[b,:,h,:] ----------------------
// grid (8 i-tiles, 64 bh); tile 64 rows x 64 cols (full HD), K=512
__global__ void k_pv() {
    int bh = blockIdx.y, b = bh >> 4, h = bh & 15;
    const float* P = g_S + (size_t)bh * NN * NN;
    const float* V = g_qkv + (size_t)(b * NN) * (3 * DD) + 2 * DD + h * HD;
    int i0 = blockIdx.x * 64;
    __shared__ float As[16][68];
    __shared__ float Bs[16][68];
    int tid = threadIdx.x, tx = tid & 15, ty = tid >> 4;
    float acc[4][4] = {};
    for (int k0 = 0; k0 < NN; k0 += 16) {
        #pragma unroll
        for (int i = 0; i < 4; i++) {
            int e = tid + i * 256;
            { int m = e >> 4, kk = e & 15;
              As[kk][m] = P[(size_t)(i0 + m) * NN + k0 + kk]; }
            { int n = e & 63, kk = e >> 6;
              Bs[kk][n] = V[(size_t)(k0 + kk) * (3 * DD) + n]; }
        }
        __syncthreads();
        #pragma unroll
        for (int k = 0; k < 16; k++) {
            float4 a4 = *(const float4*)&As[k][ty * 4];
            float4 b4 = *(const float4*)&Bs[k][tx * 4];
            float ra[4] = {a4.x, a4.y, a4.z, a4.w};
            float rb[4] = {b4.x, b4.y, b4.z, b4.w};
            #pragma unroll
            for (int i = 0; i < 4; i++)
                #pragma unroll
                for (int j = 0; j < 4; j++)
                    acc[i][j] += ra[i] * rb[j];
        }
        __syncthreads();
    }
    #pragma unroll
    for (int i = 0; i < 4; i++) {
        int ii = i0 + ty * 4 + i;
        #pragma unroll
        for (int j = 0; j < 4; j++) {
            int d = tx * 4 + j;
            g_attnout[(size_t)(b * NN + ii) * DD + h * HD + d] = acc[i][j];
        }
    }
}

// ---------------- launch -----------------------------------------------------
extern "C" void kernel_launch(void* const* d_in, const int* in_sizes, int n_in,
                              void* d_out, int out_size) {
    (void)in_sizes; (void)n_in; (void)out_size;
    const float* x      = (const float*)d_in[0];
    const float* t_emb  = (const float*)d_in[1];
    const float* rp     = (const float*)d_in[2];
    const int*   amask  = (const int*)  d_in[3];
    const float* w_ada  = (const float*)d_in[4];
    const float* b_ada  = (const float*)d_in[5];
    const float* g1     = (const float*)d_in[6];
    const float* beta1  = (const float*)d_in[7];
    const float* g2     = (const float*)d_in[8];
    const float* beta2  = (const float*)d_in[9];
    const float* w_qkv  = (const float*)d_in[10];
    const float* b_qkv  = (const float*)d_in[11];
    const float* w_proj = (const float*)d_in[12];
    const float* b_proj = (const float*)d_in[13];
    const float* w_rp1  = (const float*)d_in[14];
    const float* b_rp1  = (const float*)d_in[15];
    const float* w_rp2  = (const float*)d_in[16];
    const float* b_rp2  = (const float*)d_in[17];
    const float* w_fc1  = (const float*)d_in[18];
    const float* b_fc1  = (const float*)d_in[19];
    const float* w_fc2  = (const float*)d_in[20];
    const float* b_fc2  = (const float*)d_in[21];
    float* out = (float*)d_out;

    float *p_xn, *p_qkv, *p_attnout, *p_x1, *p_h;
    cudaGetSymbolAddress((void**)&p_xn,      g_xn);
    cudaGetSymbolAddress((void**)&p_qkv,     g_qkv);
    cudaGetSymbolAddress((void**)&p_attnout, g_attnout);
    cudaGetSymbolAddress((void**)&p_x1,      g_x1);
    cudaGetSymbolAddress((void**)&p_h,       g_h);

    // 1. adaLN modulation vector
    k_mod<<<(BB * MODD * 32 + 255) / 256, 256>>>(t_emb, w_ada, b_ada);

    // 2. LN1 + modulate (shift_s @0, scale_s @1024)
    k_ln_mod<<<TOK, 256>>>(x, g1, beta1, 0, DD, p_xn);

    // 3. QKV projection [2048,1024]x[3072,1024]^T
    k_gemm_bt<<<dim3(3 * DD / 64, TOK / 64), 256>>>(p_xn, w_qkv, b_qkv, p_qkv,
                                                    3 * DD, DD, 0, nullptr, 0);

    // 4. rel-pos bias MLP -> g_bias
    k_bias<<<BB * NN, 256>>>(rp, w_rp1, b_rp1, w_rp2, b_rp2);

    // 5. scores = scale*QK^T + bias, mask -> g_S
    k_scores<<<dim3(8, 8, BB * HH), 256>>>(amask);

    // 6. softmax rows
    k_softmax<<<BB * HH * NN, 128>>>();

    // 7. P @ V -> g_attnout
    k_pv<<<dim3(8, BB * HH), 256>>>();

    // 8. proj + gate_s residual: x1 = x + gate_s * (attnout @ Wp^T + bp)
    k_gemm_bt<<<dim3(DD / 64, TOK / 64), 256>>>(p_attnout, w_proj, b_proj, p_x1,
                                                DD, DD, 1, x, 2 * DD);

    // 9. LN2 + modulate (shift_m @3072, scale_m @4096)
    k_ln_mod<<<TOK, 256>>>(p_x1, g2, beta2, 3 * DD, 4 * DD, p_xn);

    // 10. fc1 + exact GELU -> g_h
    k_gemm_bt<<<dim3(HID / 64, TOK / 64), 256>>>(p_xn, w_fc1, b_fc1, p_h,
                                                 HID, DD, 2, nullptr, 0);

    // 11. fc2 + gate_m residual -> out
    k_gemm_bt<<<dim3(DD / 64, TOK / 64), 256>>>(p_h, w_fc2, b_fc2, out,
                                                DD, HID, 1, p_x1, 5 * DD);
}